// round 14
// baseline (speedup 1.0000x reference)
#include <cuda_runtime.h>
#include <cuda_fp16.h>
#include <cstdint>
#include <cstddef>

// ---------------- problem constants ----------------
#define D_MODEL  1024
#define D_STATE  16
#define D_INNER  2048
#define DT_RANK  64
#define BATCH    2
#define SEQ      2048
#define NROWS    (BATCH * SEQ)           // 4096
#define DBC_COLS 96
#define SPLITK   8

// ---------------- scratch (static device globals; no allocation) ----------------
__device__ float  g_xr  [(size_t)NROWS * (2 * D_INNER)];
__device__ float  g_u   [(size_t)NROWS * D_INNER];
__device__ float  g_dbc [(size_t)NROWS * DBC_COLS];
__device__ float  g_dt  [(size_t)NROWS * D_INNER];
__device__ float  g_sp  [(size_t)SPLITK * NROWS * DBC_COLS];
__device__ __half g_xh  [(size_t)NROWS * D_MODEL];
__device__ __half g_uh  [(size_t)NROWS * D_INNER];
__device__ __half g_dbch[(size_t)NROWS * DBC_COLS];
__device__ __half g_yh  [(size_t)NROWS * D_INNER];
__device__ __half g_wt  [(size_t)8 * 1024 * 1024];

// region offsets (halves)
#define WT_IN   ((size_t)0)
#define WT_XP   ((size_t)4096 * 1024)
#define WT_DT   (WT_XP + (size_t)96 * 2048)
#define WT_OUT  (WT_DT + (size_t)2048 * 64)

// ---------------- helpers ----------------
__device__ __forceinline__ float silu_f(float x) { return x / (1.0f + __expf(-x)); }
__device__ __forceinline__ float softplus_f(float x) { return (x > 20.0f) ? x : log1pf(__expf(x)); }
__device__ __forceinline__ uint32_t smem_u32(const void* p) {
    uint32_t a;
    asm("{ .reg .u64 t; cvta.to.shared.u64 t, %1; cvt.u32.u64 %0, t; }" : "=r"(a) : "l"(p));
    return a;
}
__device__ __forceinline__ void mma_f16(float* d, const uint32_t* a, const uint32_t* b) {
    asm volatile(
        "mma.sync.aligned.m16n8k16.row.col.f32.f16.f16.f32 "
        "{%0,%1,%2,%3}, {%4,%5,%6,%7}, {%8,%9}, {%0,%1,%2,%3};"
        : "+f"(d[0]), "+f"(d[1]), "+f"(d[2]), "+f"(d[3])
        : "r"(a[0]), "r"(a[1]), "r"(a[2]), "r"(a[3]), "r"(b[0]), "r"(b[1]));
}
__device__ __forceinline__ void ldsm4(uint32_t& r0, uint32_t& r1, uint32_t& r2, uint32_t& r3,
                                      uint32_t addr) {
    asm volatile("ldmatrix.sync.aligned.m8n8.x4.shared.b16 {%0,%1,%2,%3}, [%4];"
                 : "=r"(r0), "=r"(r1), "=r"(r2), "=r"(r3) : "r"(addr));
}
__device__ __forceinline__ void cpa16(uint32_t dst, const void* src) {
    asm volatile("cp.async.cg.shared.global [%0], [%1], 16;" :: "r"(dst), "l"(src));
}
__device__ __forceinline__ void cp_commit() {
    asm volatile("cp.async.commit_group;" ::: "memory");
}
template<int N> __device__ __forceinline__ void cp_wait() {
    asm volatile("cp.async.wait_group %0;" :: "n"(N) : "memory");
}
__device__ __forceinline__ void sts_zero16(uint32_t addr) {
    asm volatile("st.shared.v4.b32 [%0], {%1,%1,%1,%1};" :: "r"(addr), "r"(0u) : "memory");
}

// ---------------- fp16 tensor-core GEMM: block 128x128, 4 warps (64x64), ----------------
// BK=64, 2-stage cp.async ring (1 sync per 64-K chunk), 2 CTAs/SM.
// C(+z*Cstride)[M, N_total] = A[M,*](lda halves) @ Wt[N,*](ldw halves)^T  (both fp16)
// mode 0: plain; mode 1: softplus(acc + bias[col]).
#define BKH 64
#define RSH 72                        // halves per smem row (144 B): 36 words, 4r%32 distinct
#define STG 2
#define TILE_HB (128 * RSH * 2)       // bytes per 128-row tile stage: 18432
#define GEMM_SMEM (STG * TILE_HB * 2) // A + B: 73728 B

__global__ __launch_bounds__(128, 2) void gemm_h(
    const __half* __restrict__ A, int lda,
    const __half* __restrict__ Wt, int ldw,
    const float* __restrict__ bias,
    float* __restrict__ C, int N_total, int K_sub, int mode, size_t Cstride)
{
    extern __shared__ __half sh[];
    const uint32_t sA = smem_u32(sh);
    const uint32_t sB = sA + STG * TILE_HB;

    const int tid  = threadIdx.x;
    const int w    = tid >> 5;
    const int l    = tid & 31;
    const int mBase = blockIdx.y * 128;
    const int nBase = blockIdx.x * 128;
    const int kOff  = blockIdx.z * K_sub;
    C += (size_t)blockIdx.z * Cstride;

    const int wm = (w & 1) * 64;
    const int wn = (w >> 1) * 64;

    const int aRowOff = (l & 7) + ((l >> 3) & 1) * 8;
    const int aColH   = ((l >> 4) & 1) * 8;
    const int bRowOff = (l & 7) + ((l >> 4) & 1) * 8;
    const int bColH   = ((l >> 3) & 1) * 8;

    float acc[4][8][4];
#pragma unroll
    for (int i = 0; i < 4; i++)
#pragma unroll
        for (int j = 0; j < 8; j++)
#pragma unroll
            for (int q = 0; q < 4; q++) acc[i][j][q] = 0.0f;

    auto issue = [&](int stage, int k0) {
        // A: 128 rows x 64 halves; one row per thread, 8 x 16B
        const __half* ap = A + (size_t)(mBase + tid) * lda + kOff + k0;
        uint32_t ad = sA + (uint32_t)stage * TILE_HB + (uint32_t)tid * (RSH * 2);
#pragma unroll
        for (int q = 0; q < 8; q++) cpa16(ad + q * 16, ap + q * 8);
        // B: 128 rows x 64 halves
        int n = nBase + tid;
        uint32_t bd = sB + (uint32_t)stage * TILE_HB + (uint32_t)tid * (RSH * 2);
        if (n < N_total) {
            const __half* bp = Wt + (size_t)n * ldw + kOff + k0;
#pragma unroll
            for (int q = 0; q < 8; q++) cpa16(bd + q * 16, bp + q * 8);
        } else {
#pragma unroll
            for (int q = 0; q < 8; q++) sts_zero16(bd + q * 16);
        }
    };

    auto compute = [&](int stage) {
        const uint32_t aB = sA + (uint32_t)stage * TILE_HB
                          + (uint32_t)((wm + aRowOff) * RSH + aColH) * 2;
        const uint32_t bB = sB + (uint32_t)stage * TILE_HB
                          + (uint32_t)((wn + bRowOff) * RSH + bColH) * 2;
#pragma unroll
        for (int s = 0; s < 4; s++) {
            uint32_t af[4][4], bf[8][2];
#pragma unroll
            for (int i = 0; i < 4; i++)
                ldsm4(af[i][0], af[i][1], af[i][2], af[i][3],
                      aB + (uint32_t)((i * 16 * RSH + s * 16) * 2));
#pragma unroll
            for (int jj = 0; jj < 4; jj++)
                ldsm4(bf[2 * jj][0], bf[2 * jj][1], bf[2 * jj + 1][0], bf[2 * jj + 1][1],
                      bB + (uint32_t)((jj * 16 * RSH + s * 16) * 2));
#pragma unroll
            for (int i = 0; i < 4; i++)
#pragma unroll
                for (int j = 0; j < 8; j++)
                    mma_f16(acc[i][j], af[i], bf[j]);
        }
    };

    const int nt = K_sub / BKH;
    issue(0, 0); cp_commit();

    for (int t = 0; t < nt; t++) {
        cp_wait<0>();                 // current chunk's data resident
        __syncthreads();              // all warps past previous compute
        if (t + 1 < nt) { issue((t + 1) & 1, (t + 1) * BKH); cp_commit(); }
        compute(t & 1);               // overlaps with next chunk's cp.async
    }

    // epilogue
#pragma unroll
    for (int i = 0; i < 4; i++) {
        int r0 = mBase + wm + i * 16 + (l >> 2);
#pragma unroll
        for (int j = 0; j < 8; j++) {
            int cc = nBase + wn + j * 8 + (l & 3) * 2;
            if (cc < N_total) {
                float2 v0, v1;
                v0.x = acc[i][j][0]; v0.y = acc[i][j][1];
                v1.x = acc[i][j][2]; v1.y = acc[i][j][3];
                if (mode == 1) {
                    float b0 = bias[cc], b1 = bias[cc + 1];
                    v0.x = softplus_f(v0.x + b0); v0.y = softplus_f(v0.y + b1);
                    v1.x = softplus_f(v1.x + b0); v1.y = softplus_f(v1.y + b1);
                }
                *reinterpret_cast<float2*>(C + (size_t)r0 * N_total + cc)       = v0;
                *reinterpret_cast<float2*>(C + (size_t)(r0 + 8) * N_total + cc) = v1;
            }
        }
    }
}

// ---------------- fp32 -> fp16 convert (vectorized) ----------------
__global__ void cvt_h(const float* __restrict__ in, __half* __restrict__ out, int n4)
{
    int i = blockIdx.x * 256 + threadIdx.x;
    if (i >= n4) return;
    float4 v = reinterpret_cast<const float4*>(in)[i];
    __half2 h0 = __float22half2_rn(make_float2(v.x, v.y));
    __half2 h1 = __float22half2_rn(make_float2(v.z, v.w));
    uint2 o; o.x = *reinterpret_cast<uint32_t*>(&h0); o.y = *reinterpret_cast<uint32_t*>(&h1);
    reinterpret_cast<uint2*>(out)[i] = o;
}

// ---------------- split-K reduction: dbc (+fp16 copy) ----------------
__global__ void reduce_split_k(float* __restrict__ dbc)
{
    int i = blockIdx.x * 256 + threadIdx.x;
    if (i >= NROWS * DBC_COLS) return;
    float s = 0.0f;
#pragma unroll
    for (int z = 0; z < SPLITK; z++)
        s += g_sp[(size_t)z * NROWS * DBC_COLS + i];
    dbc[i] = s;
    g_dbch[i] = __float2half_rn(s);
}

// ---------------- weight transpose to fp16 ----------------
__global__ void transpose_h(const float* __restrict__ in, __half* __restrict__ out, int K, int N)
{
    __shared__ float t[32][33];
    const int n0 = blockIdx.x * 32, k0 = blockIdx.y * 32;
    for (int r = threadIdx.y; r < 32; r += 8)
        t[r][threadIdx.x] = in[(size_t)(k0 + r) * N + n0 + threadIdx.x];
    __syncthreads();
    for (int r = threadIdx.y; r < 32; r += 8)
        out[(size_t)(n0 + r) * K + k0 + threadIdx.x] = __float2half_rn(t[threadIdx.x][r]);
}

// ---------------- causal depthwise conv1d + silu (float4), writes fp32 + fp16 ----------------
__global__ void conv_silu4b(const float* __restrict__ conv_w,
                            const float* __restrict__ conv_b)
{
    int idx = blockIdx.x * 256 + threadIdx.x;
    if (idx >= NROWS * (D_INNER / 4)) return;
    int d4  = idx & (D_INNER / 4 - 1);
    int row = idx >> 9;
    int l   = row & (SEQ - 1);
    int b   = row >> 11;
    int d   = d4 * 4;

    const float4* cw4 = reinterpret_cast<const float4*>(conv_w);
    float4 wa = cw4[d + 0];
    float4 wb = cw4[d + 1];
    float4 wc = cw4[d + 2];
    float4 wd = cw4[d + 3];
    float4 acc = *reinterpret_cast<const float4*>(conv_b + d);

    const size_t base = ((size_t)b * SEQ) * (2 * D_INNER) + d;
    float4 xv[4];
#pragma unroll
    for (int k = 0; k < 4; k++) {
        int ll = l - 3 + k;
        xv[k] = (ll >= 0) ? *reinterpret_cast<const float4*>(&g_xr[base + (size_t)ll * (2 * D_INNER)])
                          : make_float4(0.f, 0.f, 0.f, 0.f);
    }
    acc.x += xv[0].x * wa.x + xv[1].x * wa.y + xv[2].x * wa.z + xv[3].x * wa.w;
    acc.y += xv[0].y * wb.x + xv[1].y * wb.y + xv[2].y * wb.z + xv[3].y * wb.w;
    acc.z += xv[0].z * wc.x + xv[1].z * wc.y + xv[2].z * wc.z + xv[3].z * wc.w;
    acc.w += xv[0].w * wd.x + xv[1].w * wd.y + xv[2].w * wd.z + xv[3].w * wd.w;

    float4 o;
    o.x = silu_f(acc.x); o.y = silu_f(acc.y); o.z = silu_f(acc.z); o.w = silu_f(acc.w);
    size_t oidx = (size_t)row * D_INNER + d;
    *reinterpret_cast<float4*>(&g_u[oidx]) = o;
    __half2 h0 = __float22half2_rn(make_float2(o.x, o.y));
    __half2 h1 = __float22half2_rn(make_float2(o.z, o.w));
    uint2 oh; oh.x = *reinterpret_cast<uint32_t*>(&h0); oh.y = *reinterpret_cast<uint32_t*>(&h1);
    *reinterpret_cast<uint2*>(&g_uh[oidx]) = oh;
}

// ---------------- selective scan: 8 lanes x 2 states per thread, 32 d/CTA ----------------
// grid (D_INNER/32, BATCH) = (64, 2) = 128 CTAs (one wave). 256 threads.
#define TCH 32
__global__ __launch_bounds__(256) void scan_k(
    const float* __restrict__ A_log,
    const float* __restrict__ Dv)
{
    __shared__ float s_dt [2][TCH][32];
    __shared__ float s_u  [2][TCH][32];
    __shared__ float s_res[2][TCH][32];
    __shared__ float s_bc [2][TCH][32];   // [0:16)=B, [16:32)=C
    __shared__ float s_y  [TCH][32];

    const int b    = blockIdx.y;
    const int d0   = blockIdx.x * 32;
    const int tid  = threadIdx.x;
    const int dloc = tid >> 3;    // 0..31
    const int n    = tid & 7;     // 0..7; thread owns states n and n+8
    const int d    = d0 + dloc;

    const float A0 = -__expf(A_log[d * D_STATE + n]);
    const float A1 = -__expf(A_log[d * D_STATE + n + 8]);
    const float Dd = Dv[d];
    float h0 = 0.0f, h1 = 0.0f;
    const size_t rowBase = (size_t)b * SEQ;

    auto load_chunk = [&](int l0, int buf) {
#pragma unroll
        for (int p = 0; p < 4; p++) {
            int e = p * 256 + tid, row = e >> 5, col = e & 31;
            size_t gRow = rowBase + l0 + row;
            s_dt [buf][row][col] = g_dt[gRow * D_INNER + d0 + col];
            s_u  [buf][row][col] = g_u [gRow * D_INNER + d0 + col];
            s_res[buf][row][col] = g_xr[gRow * (2 * D_INNER) + D_INNER + d0 + col];
            s_bc [buf][row][col] = g_dbc[gRow * DBC_COLS + DT_RANK + col];
        }
    };

    load_chunk(0, 0);
    __syncthreads();

    const int NCH = SEQ / TCH;
    for (int c = 0; c < NCH; c++) {
        const int buf = c & 1;
        if (c + 1 < NCH) load_chunk((c + 1) * TCH, buf ^ 1);

#pragma unroll 8
        for (int t = 0; t < TCH; t++) {
            float dt = s_dt[buf][t][dloc];
            float u  = s_u [buf][t][dloc];
            float B0 = s_bc[buf][t][n];
            float B1 = s_bc[buf][t][n + 8];
            float C0 = s_bc[buf][t][16 + n];
            float C1 = s_bc[buf][t][24 + n];
            float du = dt * u;
            h0 = fmaf(h0, __expf(dt * A0), du * B0);
            h1 = fmaf(h1, __expf(dt * A1), du * B1);
            float v = fmaf(h1, C1, h0 * C0);
            v += __shfl_xor_sync(0xffffffffu, v, 4);
            v += __shfl_xor_sync(0xffffffffu, v, 2);
            v += __shfl_xor_sync(0xffffffffu, v, 1);
            if (n == 0) s_y[t][dloc] = fmaf(Dd, u, v);
        }
        __syncthreads();

        // gated, coalesced y write (fp16)
#pragma unroll
        for (int p = 0; p < 4; p++) {
            int e = p * 256 + tid, row = e >> 5, col = e & 31;
            float r = s_res[buf][row][col];
            g_yh[(rowBase + c * TCH + row) * D_INNER + d0 + col] =
                __float2half_rn(s_y[row][col] * silu_f(r));
        }
        __syncthreads();
    }
}

// ---------------- launch ----------------
extern "C" void kernel_launch(void* const* d_in, const int* in_sizes, int n_in,
                              void* d_out, int out_size)
{
    const float* x          = (const float*)d_in[0];
    const float* in_proj_w  = (const float*)d_in[1];
    const float* conv_w     = (const float*)d_in[2];
    const float* conv_b     = (const float*)d_in[3];
    const float* x_proj_w   = (const float*)d_in[4];
    const float* dt_proj_w  = (const float*)d_in[5];
    const float* dt_proj_b  = (const float*)d_in[6];
    const float* A_log      = (const float*)d_in[7];
    const float* Dv         = (const float*)d_in[8];
    const float* out_proj_w = (const float*)d_in[9];
    float* out = (float*)d_out;

    float*  xr   = nullptr; cudaGetSymbolAddress((void**)&xr,   g_xr);
    float*  dbc  = nullptr; cudaGetSymbolAddress((void**)&dbc,  g_dbc);
    float*  dt   = nullptr; cudaGetSymbolAddress((void**)&dt,   g_dt);
    float*  sp   = nullptr; cudaGetSymbolAddress((void**)&sp,   g_sp);
    __half* xh   = nullptr; cudaGetSymbolAddress((void**)&xh,   g_xh);
    __half* uh   = nullptr; cudaGetSymbolAddress((void**)&uh,   g_uh);
    __half* dbch = nullptr; cudaGetSymbolAddress((void**)&dbch, g_dbch);
    __half* yh   = nullptr; cudaGetSymbolAddress((void**)&yh,   g_yh);
    __half* wt   = nullptr; cudaGetSymbolAddress((void**)&wt,   g_wt);

    static int smem_set = 0;
    if (!smem_set) {
        cudaFuncSetAttribute(gemm_h, cudaFuncAttributeMaxDynamicSharedMemorySize, GEMM_SMEM);
        smem_set = 1;
    }

    dim3 tb(32, 8);

    // idx 0: x -> fp16
    cvt_h<<<(NROWS * D_MODEL / 4 + 255) / 256, 256>>>(x, xh, NROWS * D_MODEL / 4);
    // idx 1-2: transposes needed by in_proj GEMM
    transpose_h<<<dim3(128, 32), tb>>>(in_proj_w, wt + WT_IN, 1024, 4096);
    transpose_h<<<dim3(3, 64), tb>>>(x_proj_w, wt + WT_XP, 2048, 96);

    // idx 3 (ncu-captured): in_proj GEMM  (4096 x 4096, K=1024)
    gemm_h<<<dim3(32, 32), 128, GEMM_SMEM>>>(
        xh, D_MODEL, wt + WT_IN, D_MODEL, nullptr, xr, 2 * D_INNER, D_MODEL, 0, 0);

    // idx 4-5: remaining transposes
    transpose_h<<<dim3(64, 2), tb>>>(dt_proj_w, wt + WT_DT, 64, 2048);
    transpose_h<<<dim3(32, 64), tb>>>(out_proj_w, wt + WT_OUT, 2048, 1024);

    // idx 6: conv + silu -> u (fp32 + fp16)
    conv_silu4b<<<(NROWS * (D_INNER / 4) + 255) / 256, 256>>>(conv_w, conv_b);

    // idx 7-8: dbc = u @ x_proj_w (4096x96, K=2048) split-K x8 + reduce
    gemm_h<<<dim3(1, 32, SPLITK), 128, GEMM_SMEM>>>(
        uh, D_INNER, wt + WT_XP, D_INNER, nullptr, sp, DBC_COLS, D_INNER / SPLITK, 0,
        (size_t)NROWS * DBC_COLS);
    reduce_split_k<<<(NROWS * DBC_COLS + 255) / 256, 256>>>(dbc);

    // idx 9: dt = softplus(dbc[:, :64] @ dt_proj_w + b)  (4096x2048, K=64)
    gemm_h<<<dim3(16, 32), 128, GEMM_SMEM>>>(
        dbch, DBC_COLS, wt + WT_DT, DT_RANK, dt_proj_b, dt, D_INNER, DT_RANK, 1, 0);

    // idx 10: selective scan + gating -> y (fp16)
    scan_k<<<dim3(D_INNER / 32, BATCH), 256>>>(A_log, Dv);

    // idx 11: out = y @ out_proj_w  (4096x1024, K=2048)
    gemm_h<<<dim3(8, 32), 128, GEMM_SMEM>>>(
        yh, D_INNER, wt + WT_OUT, D_INNER, nullptr, out, D_MODEL, D_INNER, 0, 0);
}

// round 15
// speedup vs baseline: 1.5581x; 1.5581x over previous
#include <cuda_runtime.h>
#include <cuda_fp16.h>
#include <cstdint>
#include <cstddef>

// ---------------- problem constants ----------------
#define D_MODEL  1024
#define D_STATE  16
#define D_INNER  2048
#define DT_RANK  64
#define BATCH    2
#define SEQ      2048
#define NROWS    (BATCH * SEQ)           // 4096
#define DBC_COLS 96
#define SPLITK   8

// ---------------- scratch (static device globals; no allocation) ----------------
__device__ float  g_xr  [(size_t)NROWS * (2 * D_INNER)];
__device__ float  g_u   [(size_t)NROWS * D_INNER];
__device__ float  g_dbc [(size_t)NROWS * DBC_COLS];
__device__ float  g_dt  [(size_t)NROWS * D_INNER];
__device__ float  g_sp  [(size_t)SPLITK * NROWS * DBC_COLS];
__device__ __half g_xh  [(size_t)NROWS * D_MODEL];
__device__ __half g_uh  [(size_t)NROWS * D_INNER];
__device__ __half g_dbch[(size_t)NROWS * DBC_COLS];
__device__ __half g_yh  [(size_t)NROWS * D_INNER];
__device__ __half g_wt  [(size_t)8 * 1024 * 1024];

// region offsets (halves)
#define WT_IN   ((size_t)0)
#define WT_XP   ((size_t)4096 * 1024)
#define WT_DT   (WT_XP + (size_t)96 * 2048)
#define WT_OUT  (WT_DT + (size_t)2048 * 64)

// ---------------- helpers ----------------
__device__ __forceinline__ float silu_f(float x) { return x / (1.0f + __expf(-x)); }
__device__ __forceinline__ float softplus_f(float x) { return (x > 20.0f) ? x : log1pf(__expf(x)); }
__device__ __forceinline__ uint32_t smem_u32(const void* p) {
    uint32_t a;
    asm("{ .reg .u64 t; cvta.to.shared.u64 t, %1; cvt.u32.u64 %0, t; }" : "=r"(a) : "l"(p));
    return a;
}
__device__ __forceinline__ void mma_f16(float* d, const uint32_t* a, const uint32_t* b) {
    asm volatile(
        "mma.sync.aligned.m16n8k16.row.col.f32.f16.f16.f32 "
        "{%0,%1,%2,%3}, {%4,%5,%6,%7}, {%8,%9}, {%0,%1,%2,%3};"
        : "+f"(d[0]), "+f"(d[1]), "+f"(d[2]), "+f"(d[3])
        : "r"(a[0]), "r"(a[1]), "r"(a[2]), "r"(a[3]), "r"(b[0]), "r"(b[1]));
}
__device__ __forceinline__ void ldsm4(uint32_t& r0, uint32_t& r1, uint32_t& r2, uint32_t& r3,
                                      uint32_t addr) {
    asm volatile("ldmatrix.sync.aligned.m8n8.x4.shared.b16 {%0,%1,%2,%3}, [%4];"
                 : "=r"(r0), "=r"(r1), "=r"(r2), "=r"(r3) : "r"(addr));
}
__device__ __forceinline__ void cpa16(uint32_t dst, const void* src) {
    asm volatile("cp.async.cg.shared.global [%0], [%1], 16;" :: "r"(dst), "l"(src));
}
__device__ __forceinline__ void cp_commit() {
    asm volatile("cp.async.commit_group;" ::: "memory");
}
template<int N> __device__ __forceinline__ void cp_wait() {
    asm volatile("cp.async.wait_group %0;" :: "n"(N) : "memory");
}
__device__ __forceinline__ void sts_zero16(uint32_t addr) {
    asm volatile("st.shared.v4.b32 [%0], {%1,%1,%1,%1};" :: "r"(addr), "r"(0u) : "memory");
}

// ---------------- fp16 tensor-core GEMM: block 128x128, 4 warps (64x64 each), ----------------
// 3-stage cp.async ring, 2 CTAs/SM.   (round-13 proven config)
// C(+z*Cstride)[M, N_total] = A[M,*](lda halves) @ Wt[N,*](ldw halves)^T  (both fp16)
// mode 0: plain; mode 1: softplus(acc + bias[col]).
#define BKH 32
#define RSH 40                       // smem row stride in halves (80 B)
#define STG 3
#define GEMM_SMEM (STG * 256 * RSH * 2)   // 61440 B

__global__ __launch_bounds__(128, 2) void gemm_h(
    const __half* __restrict__ A, int lda,
    const __half* __restrict__ Wt, int ldw,
    const float* __restrict__ bias,
    float* __restrict__ C, int N_total, int K_sub, int mode, size_t Cstride)
{
    extern __shared__ __half sh[];
    const uint32_t sA = smem_u32(sh);
    const uint32_t sB = sA + STG * 128 * RSH * 2;

    const int tid  = threadIdx.x;
    const int w    = tid >> 5;
    const int l    = tid & 31;
    const int mBase = blockIdx.y * 128;
    const int nBase = blockIdx.x * 128;
    const int kOff  = blockIdx.z * K_sub;
    C += (size_t)blockIdx.z * Cstride;

    const int wm = (w & 1) * 64;
    const int wn = (w >> 1) * 64;

    const int aRowOff = (l & 7) + ((l >> 3) & 1) * 8;
    const int aColH   = ((l >> 4) & 1) * 8;
    const int bRowOff = (l & 7) + ((l >> 4) & 1) * 8;
    const int bColH   = ((l >> 3) & 1) * 8;

    float acc[4][8][4];
#pragma unroll
    for (int i = 0; i < 4; i++)
#pragma unroll
        for (int j = 0; j < 8; j++)
#pragma unroll
            for (int q = 0; q < 4; q++) acc[i][j][q] = 0.0f;

    auto issue = [&](int stage, int k0) {
        // A: 128 rows x 32 halves; one row per thread, 4 x 16B
        const __half* ap = A + (size_t)(mBase + tid) * lda + kOff + k0;
        uint32_t ad = sA + (uint32_t)(stage * 128 + tid) * (RSH * 2);
#pragma unroll
        for (int q = 0; q < 4; q++) cpa16(ad + q * 16, ap + q * 8);
        // B: 128 rows x 32 halves; one row per thread
        int n = nBase + tid;
        uint32_t bd = sB + (uint32_t)(stage * 128 + tid) * (RSH * 2);
        if (n < N_total) {
            const __half* bp = Wt + (size_t)n * ldw + kOff + k0;
#pragma unroll
            for (int q = 0; q < 4; q++) cpa16(bd + q * 16, bp + q * 8);
        } else {
#pragma unroll
            for (int q = 0; q < 4; q++) sts_zero16(bd + q * 16);
        }
    };

    auto compute = [&](int stage) {
        const uint32_t aB = sA + (uint32_t)((stage * 128 + wm + aRowOff) * RSH + aColH) * 2;
        const uint32_t bB = sB + (uint32_t)((stage * 128 + wn + bRowOff) * RSH + bColH) * 2;
#pragma unroll
        for (int s = 0; s < 2; s++) {
            uint32_t af[4][4], bf[8][2];
#pragma unroll
            for (int i = 0; i < 4; i++)
                ldsm4(af[i][0], af[i][1], af[i][2], af[i][3],
                      aB + (uint32_t)((i * 16 * RSH + s * 16) * 2));
#pragma unroll
            for (int jj = 0; jj < 4; jj++)
                ldsm4(bf[2 * jj][0], bf[2 * jj][1], bf[2 * jj + 1][0], bf[2 * jj + 1][1],
                      bB + (uint32_t)((jj * 16 * RSH + s * 16) * 2));
#pragma unroll
            for (int i = 0; i < 4; i++)
#pragma unroll
                for (int j = 0; j < 8; j++)
                    mma_f16(acc[i][j], af[i], bf[j]);
        }
    };

    const int nt = K_sub / BKH;
    int fetch = 0;
    for (; fetch < STG - 1 && fetch < nt; fetch++) { issue(fetch, fetch * BKH); cp_commit(); }

    for (int t = 0; t < nt; t++) {
        cp_wait<STG - 2>();
        __syncthreads();
        if (fetch < nt) { issue(fetch % STG, fetch * BKH); fetch++; }
        cp_commit();                    // always commit (possibly empty) to keep counts uniform
        compute(t % STG);
    }

    // epilogue
#pragma unroll
    for (int i = 0; i < 4; i++) {
        int r0 = mBase + wm + i * 16 + (l >> 2);
#pragma unroll
        for (int j = 0; j < 8; j++) {
            int cc = nBase + wn + j * 8 + (l & 3) * 2;
            if (cc < N_total) {
                float2 v0, v1;
                v0.x = acc[i][j][0]; v0.y = acc[i][j][1];
                v1.x = acc[i][j][2]; v1.y = acc[i][j][3];
                if (mode == 1) {
                    float b0 = bias[cc], b1 = bias[cc + 1];
                    v0.x = softplus_f(v0.x + b0); v0.y = softplus_f(v0.y + b1);
                    v1.x = softplus_f(v1.x + b0); v1.y = softplus_f(v1.y + b1);
                }
                *reinterpret_cast<float2*>(C + (size_t)r0 * N_total + cc)       = v0;
                *reinterpret_cast<float2*>(C + (size_t)(r0 + 8) * N_total + cc) = v1;
            }
        }
    }
}

// ---------------- fp32 -> fp16 convert (vectorized) ----------------
__global__ void cvt_h(const float* __restrict__ in, __half* __restrict__ out, int n4)
{
    int i = blockIdx.x * 256 + threadIdx.x;
    if (i >= n4) return;
    float4 v = reinterpret_cast<const float4*>(in)[i];
    __half2 h0 = __float22half2_rn(make_float2(v.x, v.y));
    __half2 h1 = __float22half2_rn(make_float2(v.z, v.w));
    uint2 o; o.x = *reinterpret_cast<uint32_t*>(&h0); o.y = *reinterpret_cast<uint32_t*>(&h1);
    reinterpret_cast<uint2*>(out)[i] = o;
}

// ---------------- split-K reduction: dbc (+fp16 copy) ----------------
__global__ void reduce_split_k(float* __restrict__ dbc)
{
    int i = blockIdx.x * 256 + threadIdx.x;
    if (i >= NROWS * DBC_COLS) return;
    float s = 0.0f;
#pragma unroll
    for (int z = 0; z < SPLITK; z++)
        s += g_sp[(size_t)z * NROWS * DBC_COLS + i];
    dbc[i] = s;
    g_dbch[i] = __float2half_rn(s);
}

// ---------------- weight transpose to fp16 ----------------
__global__ void transpose_h(const float* __restrict__ in, __half* __restrict__ out, int K, int N)
{
    __shared__ float t[32][33];
    const int n0 = blockIdx.x * 32, k0 = blockIdx.y * 32;
    for (int r = threadIdx.y; r < 32; r += 8)
        t[r][threadIdx.x] = in[(size_t)(k0 + r) * N + n0 + threadIdx.x];
    __syncthreads();
    for (int r = threadIdx.y; r < 32; r += 8)
        out[(size_t)(n0 + r) * K + k0 + threadIdx.x] = __float2half_rn(t[threadIdx.x][r]);
}

// ---------------- causal depthwise conv1d + silu (float4), writes fp32 + fp16 ----------------
__global__ void conv_silu4b(const float* __restrict__ conv_w,
                            const float* __restrict__ conv_b)
{
    int idx = blockIdx.x * 256 + threadIdx.x;
    if (idx >= NROWS * (D_INNER / 4)) return;
    int d4  = idx & (D_INNER / 4 - 1);
    int row = idx >> 9;
    int l   = row & (SEQ - 1);
    int b   = row >> 11;
    int d   = d4 * 4;

    const float4* cw4 = reinterpret_cast<const float4*>(conv_w);
    float4 wa = cw4[d + 0];
    float4 wb = cw4[d + 1];
    float4 wc = cw4[d + 2];
    float4 wd = cw4[d + 3];
    float4 acc = *reinterpret_cast<const float4*>(conv_b + d);

    const size_t base = ((size_t)b * SEQ) * (2 * D_INNER) + d;
    float4 xv[4];
#pragma unroll
    for (int k = 0; k < 4; k++) {
        int ll = l - 3 + k;
        xv[k] = (ll >= 0) ? *reinterpret_cast<const float4*>(&g_xr[base + (size_t)ll * (2 * D_INNER)])
                          : make_float4(0.f, 0.f, 0.f, 0.f);
    }
    acc.x += xv[0].x * wa.x + xv[1].x * wa.y + xv[2].x * wa.z + xv[3].x * wa.w;
    acc.y += xv[0].y * wb.x + xv[1].y * wb.y + xv[2].y * wb.z + xv[3].y * wb.w;
    acc.z += xv[0].z * wc.x + xv[1].z * wc.y + xv[2].z * wc.z + xv[3].z * wc.w;
    acc.w += xv[0].w * wd.x + xv[1].w * wd.y + xv[2].w * wd.z + xv[3].w * wd.w;

    float4 o;
    o.x = silu_f(acc.x); o.y = silu_f(acc.y); o.z = silu_f(acc.z); o.w = silu_f(acc.w);
    size_t oidx = (size_t)row * D_INNER + d;
    *reinterpret_cast<float4*>(&g_u[oidx]) = o;
    __half2 h0 = __float22half2_rn(make_float2(o.x, o.y));
    __half2 h1 = __float22half2_rn(make_float2(o.z, o.w));
    uint2 oh; oh.x = *reinterpret_cast<uint32_t*>(&h0); oh.y = *reinterpret_cast<uint32_t*>(&h1);
    *reinterpret_cast<uint2*>(&g_uh[oidx]) = oh;
}

// ---------------- selective scan: 8 lanes x 2 states per thread, 32 d/CTA ----------------
// grid (D_INNER/32, BATCH) = (64, 2) = 128 CTAs (one wave). 256 threads.
#define TCH 32
__global__ __launch_bounds__(256) void scan_k(
    const float* __restrict__ A_log,
    const float* __restrict__ Dv)
{
    __shared__ float s_dt [2][TCH][32];
    __shared__ float s_u  [2][TCH][32];
    __shared__ float s_res[2][TCH][32];
    __shared__ float s_bc [2][TCH][32];   // [0:16)=B, [16:32)=C
    __shared__ float s_y  [TCH][32];

    const int b    = blockIdx.y;
    const int d0   = blockIdx.x * 32;
    const int tid  = threadIdx.x;
    const int dloc = tid >> 3;    // 0..31
    const int n    = tid & 7;     // 0..7; thread owns states n and n+8
    const int d    = d0 + dloc;

    const float A0 = -__expf(A_log[d * D_STATE + n]);
    const float A1 = -__expf(A_log[d * D_STATE + n + 8]);
    const float Dd = Dv[d];
    float h0 = 0.0f, h1 = 0.0f;
    const size_t rowBase = (size_t)b * SEQ;

    auto load_chunk = [&](int l0, int buf) {
#pragma unroll
        for (int p = 0; p < 4; p++) {
            int e = p * 256 + tid, row = e >> 5, col = e & 31;
            size_t gRow = rowBase + l0 + row;
            s_dt [buf][row][col] = g_dt[gRow * D_INNER + d0 + col];
            s_u  [buf][row][col] = g_u [gRow * D_INNER + d0 + col];
            s_res[buf][row][col] = g_xr[gRow * (2 * D_INNER) + D_INNER + d0 + col];
            s_bc [buf][row][col] = g_dbc[gRow * DBC_COLS + DT_RANK + col];
        }
    };

    load_chunk(0, 0);
    __syncthreads();

    const int NCH = SEQ / TCH;
    for (int c = 0; c < NCH; c++) {
        const int buf = c & 1;
        if (c + 1 < NCH) load_chunk((c + 1) * TCH, buf ^ 1);

#pragma unroll 8
        for (int t = 0; t < TCH; t++) {
            float dt = s_dt[buf][t][dloc];
            float u  = s_u [buf][t][dloc];
            float B0 = s_bc[buf][t][n];
            float B1 = s_bc[buf][t][n + 8];
            float C0 = s_bc[buf][t][16 + n];
            float C1 = s_bc[buf][t][24 + n];
            float du = dt * u;
            h0 = fmaf(h0, __expf(dt * A0), du * B0);
            h1 = fmaf(h1, __expf(dt * A1), du * B1);
            float v = fmaf(h1, C1, h0 * C0);
            v += __shfl_xor_sync(0xffffffffu, v, 4);
            v += __shfl_xor_sync(0xffffffffu, v, 2);
            v += __shfl_xor_sync(0xffffffffu, v, 1);
            if (n == 0) s_y[t][dloc] = fmaf(Dd, u, v);
        }
        __syncthreads();

        // gated, coalesced y write (fp16)
#pragma unroll
        for (int p = 0; p < 4; p++) {
            int e = p * 256 + tid, row = e >> 5, col = e & 31;
            float r = s_res[buf][row][col];
            g_yh[(rowBase + c * TCH + row) * D_INNER + d0 + col] =
                __float2half_rn(s_y[row][col] * silu_f(r));
        }
        __syncthreads();
    }
}

// ---------------- launch ----------------
extern "C" void kernel_launch(void* const* d_in, const int* in_sizes, int n_in,
                              void* d_out, int out_size)
{
    const float* x          = (const float*)d_in[0];
    const float* in_proj_w  = (const float*)d_in[1];
    const float* conv_w     = (const float*)d_in[2];
    const float* conv_b     = (const float*)d_in[3];
    const float* x_proj_w   = (const float*)d_in[4];
    const float* dt_proj_w  = (const float*)d_in[5];
    const float* dt_proj_b  = (const float*)d_in[6];
    const float* A_log      = (const float*)d_in[7];
    const float* Dv         = (const float*)d_in[8];
    const float* out_proj_w = (const float*)d_in[9];
    float* out = (float*)d_out;

    float*  xr   = nullptr; cudaGetSymbolAddress((void**)&xr,   g_xr);
    float*  dbc  = nullptr; cudaGetSymbolAddress((void**)&dbc,  g_dbc);
    float*  dt   = nullptr; cudaGetSymbolAddress((void**)&dt,   g_dt);
    float*  sp   = nullptr; cudaGetSymbolAddress((void**)&sp,   g_sp);
    __half* xh   = nullptr; cudaGetSymbolAddress((void**)&xh,   g_xh);
    __half* uh   = nullptr; cudaGetSymbolAddress((void**)&uh,   g_uh);
    __half* dbch = nullptr; cudaGetSymbolAddress((void**)&dbch, g_dbch);
    __half* yh   = nullptr; cudaGetSymbolAddress((void**)&yh,   g_yh);
    __half* wt   = nullptr; cudaGetSymbolAddress((void**)&wt,   g_wt);

    static int smem_set = 0;
    if (!smem_set) {
        cudaFuncSetAttribute(gemm_h, cudaFuncAttributeMaxDynamicSharedMemorySize, GEMM_SMEM);
        smem_set = 1;
    }

    dim3 tb(32, 8);

    // idx 0: x -> fp16
    cvt_h<<<(NROWS * D_MODEL / 4 + 255) / 256, 256>>>(x, xh, NROWS * D_MODEL / 4);
    // idx 1-2: transposes needed by in_proj GEMM
    transpose_h<<<dim3(128, 32), tb>>>(in_proj_w, wt + WT_IN, 1024, 4096);
    transpose_h<<<dim3(3, 64), tb>>>(x_proj_w, wt + WT_XP, 2048, 96);

    // idx 3 (ncu-captured): in_proj GEMM  (4096 x 4096, K=1024)
    gemm_h<<<dim3(32, 32), 128, GEMM_SMEM>>>(
        xh, D_MODEL, wt + WT_IN, D_MODEL, nullptr, xr, 2 * D_INNER, D_MODEL, 0, 0);

    // idx 4-5: remaining transposes
    transpose_h<<<dim3(64, 2), tb>>>(dt_proj_w, wt + WT_DT, 64, 2048);
    transpose_h<<<dim3(32, 64), tb>>>(out_proj_w, wt + WT_OUT, 2048, 1024);

    // idx 6: conv + silu -> u (fp32 + fp16)
    conv_silu4b<<<(NROWS * (D_INNER / 4) + 255) / 256, 256>>>(conv_w, conv_b);

    // idx 7-8: dbc = u @ x_proj_w (4096x96, K=2048) split-K x8 + reduce
    gemm_h<<<dim3(1, 32, SPLITK), 128, GEMM_SMEM>>>(
        uh, D_INNER, wt + WT_XP, D_INNER, nullptr, sp, DBC_COLS, D_INNER / SPLITK, 0,
        (size_t)NROWS * DBC_COLS);
    reduce_split_k<<<(NROWS * DBC_COLS + 255) / 256, 256>>>(dbc);

    // idx 9: dt = softplus(dbc[:, :64] @ dt_proj_w + b)  (4096x2048, K=64)
    gemm_h<<<dim3(16, 32), 128, GEMM_SMEM>>>(
        dbch, DBC_COLS, wt + WT_DT, DT_RANK, dt_proj_b, dt, D_INNER, DT_RANK, 1, 0);

    // idx 10: selective scan + gating -> y (fp16)
    scan_k<<<dim3(D_INNER / 32, BATCH), 256>>>(A_log, Dv);

    // idx 11: out = y @ out_proj_w  (4096x1024, K=2048)
    gemm_h<<<dim3(8, 32), 128, GEMM_SMEM>>>(
        yh, D_INNER, wt + WT_OUT, D_INNER, nullptr, out, D_MODEL, D_INNER, 0, 0);
}

// round 16
// speedup vs baseline: 1.8079x; 1.1603x over previous
#include <cuda_runtime.h>
#include <cuda_fp16.h>
#include <cstdint>
#include <cstddef>

// ---------------- problem constants ----------------
#define D_MODEL  1024
#define D_STATE  16
#define D_INNER  2048
#define DT_RANK  64
#define BATCH    2
#define SEQ      2048
#define NROWS    (BATCH * SEQ)           // 4096
#define DBC_COLS 96
#define SPLITK   8

// ---------------- scratch (static device globals; no allocation) ----------------
__device__ float  g_dbc [(size_t)NROWS * DBC_COLS];
__device__ float  g_dt  [(size_t)NROWS * D_INNER];
__device__ float  g_sp  [(size_t)SPLITK * NROWS * DBC_COLS];
__device__ __half g_xrh [(size_t)NROWS * (2 * D_INNER)];  // cols [0,2048)=xb, [2048,4096)=res
__device__ __half g_xh  [(size_t)NROWS * D_MODEL];
__device__ __half g_uh  [(size_t)NROWS * D_INNER];
__device__ __half g_dbch[(size_t)NROWS * DBC_COLS];
__device__ __half g_yh  [(size_t)NROWS * D_INNER];
__device__ __half g_wt  [(size_t)8 * 1024 * 1024];

// region offsets (halves)
#define WT_IN   ((size_t)0)
#define WT_XP   ((size_t)4096 * 1024)
#define WT_DT   (WT_XP + (size_t)96 * 2048)
#define WT_OUT  (WT_DT + (size_t)2048 * 64)

// ---------------- helpers ----------------
__device__ __forceinline__ float silu_f(float x) { return x / (1.0f + __expf(-x)); }
__device__ __forceinline__ float softplus_f(float x) { return (x > 20.0f) ? x : log1pf(__expf(x)); }
__device__ __forceinline__ uint32_t smem_u32(const void* p) {
    uint32_t a;
    asm("{ .reg .u64 t; cvta.to.shared.u64 t, %1; cvt.u32.u64 %0, t; }" : "=r"(a) : "l"(p));
    return a;
}
__device__ __forceinline__ void mma_f16(float* d, const uint32_t* a, const uint32_t* b) {
    asm volatile(
        "mma.sync.aligned.m16n8k16.row.col.f32.f16.f16.f32 "
        "{%0,%1,%2,%3}, {%4,%5,%6,%7}, {%8,%9}, {%0,%1,%2,%3};"
        : "+f"(d[0]), "+f"(d[1]), "+f"(d[2]), "+f"(d[3])
        : "r"(a[0]), "r"(a[1]), "r"(a[2]), "r"(a[3]), "r"(b[0]), "r"(b[1]));
}
__device__ __forceinline__ void ldsm4(uint32_t& r0, uint32_t& r1, uint32_t& r2, uint32_t& r3,
                                      uint32_t addr) {
    asm volatile("ldmatrix.sync.aligned.m8n8.x4.shared.b16 {%0,%1,%2,%3}, [%4];"
                 : "=r"(r0), "=r"(r1), "=r"(r2), "=r"(r3) : "r"(addr));
}
__device__ __forceinline__ void cpa16(uint32_t dst, const void* src) {
    asm volatile("cp.async.cg.shared.global [%0], [%1], 16;" :: "r"(dst), "l"(src));
}
__device__ __forceinline__ void cp_commit() {
    asm volatile("cp.async.commit_group;" ::: "memory");
}
template<int N> __device__ __forceinline__ void cp_wait() {
    asm volatile("cp.async.wait_group %0;" :: "n"(N) : "memory");
}
__device__ __forceinline__ void sts_zero16(uint32_t addr) {
    asm volatile("st.shared.v4.b32 [%0], {%1,%1,%1,%1};" :: "r"(addr), "r"(0u) : "memory");
}

// ---------------- fp16 tensor-core GEMM: block 128x128, 8 warps (32x64 tiles), ----------------
// 3-stage cp.async ring, 2 CTAs/SM -> 16 warps/SM.
// C(+z*Cstride) = A[M,*](lda halves) @ Wt[N,*](ldw halves)^T  (both fp16)
// mode 0: fp32 store; mode 1: fp32 softplus(acc+bias); mode 2: fp16 store.
#define BKH 32
#define RSH 40                       // smem row stride in halves (80 B)
#define STG 3
#define GEMM_SMEM (STG * 256 * RSH * 2)   // 61440 B

__global__ __launch_bounds__(256, 2) void gemm_h(
    const __half* __restrict__ A, int lda,
    const __half* __restrict__ Wt, int ldw,
    const float* __restrict__ bias,
    float* __restrict__ C, int N_total, int K_sub, int mode, size_t Cstride)
{
    extern __shared__ __half sh[];
    const uint32_t sA = smem_u32(sh);
    const uint32_t sB = sA + STG * 128 * RSH * 2;

    const int tid  = threadIdx.x;
    const int w    = tid >> 5;
    const int l    = tid & 31;
    const int mBase = blockIdx.y * 128;
    const int nBase = blockIdx.x * 128;
    const int kOff  = blockIdx.z * K_sub;

    const int wm = (w & 3) * 32;      // 4 warps in M
    const int wn = (w >> 2) * 64;     // 2 warps in N

    const int aRowOff = (l & 7) + ((l >> 3) & 1) * 8;
    const int aColH   = ((l >> 4) & 1) * 8;
    const int bRowOff = (l & 7) + ((l >> 4) & 1) * 8;
    const int bColH   = ((l >> 3) & 1) * 8;

    float acc[2][8][4];
#pragma unroll
    for (int i = 0; i < 2; i++)
#pragma unroll
        for (int j = 0; j < 8; j++)
#pragma unroll
            for (int q = 0; q < 4; q++) acc[i][j][q] = 0.0f;

    // loader: 256 threads, A/B 128 rows x 32 halves; thread -> row tid>>1, 16-half chunk tid&1
    const int ldRow = tid >> 1;
    const int ldC   = (tid & 1) * 16;

    auto issue = [&](int stage, int k0) {
        const __half* ap = A + (size_t)(mBase + ldRow) * lda + kOff + k0 + ldC;
        uint32_t ad = sA + (uint32_t)(stage * 128 + ldRow) * (RSH * 2) + (uint32_t)ldC * 2;
        cpa16(ad, ap);
        cpa16(ad + 16, ap + 8);
        int n = nBase + ldRow;
        uint32_t bd = sB + (uint32_t)(stage * 128 + ldRow) * (RSH * 2) + (uint32_t)ldC * 2;
        if (n < N_total) {
            const __half* bp = Wt + (size_t)n * ldw + kOff + k0 + ldC;
            cpa16(bd, bp);
            cpa16(bd + 16, bp + 8);
        } else {
            sts_zero16(bd);
            sts_zero16(bd + 16);
        }
    };

    auto compute = [&](int stage) {
        const uint32_t aB = sA + (uint32_t)((stage * 128 + wm + aRowOff) * RSH + aColH) * 2;
        const uint32_t bB = sB + (uint32_t)((stage * 128 + wn + bRowOff) * RSH + bColH) * 2;
#pragma unroll
        for (int s = 0; s < 2; s++) {
            uint32_t af[2][4], bf[8][2];
#pragma unroll
            for (int i = 0; i < 2; i++)
                ldsm4(af[i][0], af[i][1], af[i][2], af[i][3],
                      aB + (uint32_t)((i * 16 * RSH + s * 16) * 2));
#pragma unroll
            for (int jj = 0; jj < 4; jj++)
                ldsm4(bf[2 * jj][0], bf[2 * jj][1], bf[2 * jj + 1][0], bf[2 * jj + 1][1],
                      bB + (uint32_t)((jj * 16 * RSH + s * 16) * 2));
#pragma unroll
            for (int i = 0; i < 2; i++)
#pragma unroll
                for (int j = 0; j < 8; j++)
                    mma_f16(acc[i][j], af[i], bf[j]);
        }
    };

    const int nt = K_sub / BKH;
    int fetch = 0;
    for (; fetch < STG - 1 && fetch < nt; fetch++) { issue(fetch, fetch * BKH); cp_commit(); }

    for (int t = 0; t < nt; t++) {
        cp_wait<STG - 2>();
        __syncthreads();
        if (fetch < nt) { issue(fetch % STG, fetch * BKH); fetch++; }
        cp_commit();                    // always commit to keep counts uniform
        compute(t % STG);
    }

    // epilogue
    float*  Cf = C + (size_t)blockIdx.z * Cstride;
    __half* Ch = reinterpret_cast<__half*>(C);
#pragma unroll
    for (int i = 0; i < 2; i++) {
        int r0 = mBase + wm + i * 16 + (l >> 2);
#pragma unroll
        for (int j = 0; j < 8; j++) {
            int cc = nBase + wn + j * 8 + (l & 3) * 2;
            if (cc < N_total) {
                float2 v0, v1;
                v0.x = acc[i][j][0]; v0.y = acc[i][j][1];
                v1.x = acc[i][j][2]; v1.y = acc[i][j][3];
                if (mode == 2) {
                    __half2 h0 = __float22half2_rn(v0);
                    __half2 h1 = __float22half2_rn(v1);
                    *reinterpret_cast<__half2*>(Ch + (size_t)r0 * N_total + cc)       = h0;
                    *reinterpret_cast<__half2*>(Ch + (size_t)(r0 + 8) * N_total + cc) = h1;
                } else {
                    if (mode == 1) {
                        float b0 = bias[cc], b1 = bias[cc + 1];
                        v0.x = softplus_f(v0.x + b0); v0.y = softplus_f(v0.y + b1);
                        v1.x = softplus_f(v1.x + b0); v1.y = softplus_f(v1.y + b1);
                    }
                    *reinterpret_cast<float2*>(Cf + (size_t)r0 * N_total + cc)       = v0;
                    *reinterpret_cast<float2*>(Cf + (size_t)(r0 + 8) * N_total + cc) = v1;
                }
            }
        }
    }
}

// ---------------- fp32 -> fp16 convert (vectorized) ----------------
__global__ void cvt_h(const float* __restrict__ in, __half* __restrict__ out, int n4)
{
    int i = blockIdx.x * 256 + threadIdx.x;
    if (i >= n4) return;
    float4 v = reinterpret_cast<const float4*>(in)[i];
    __half2 h0 = __float22half2_rn(make_float2(v.x, v.y));
    __half2 h1 = __float22half2_rn(make_float2(v.z, v.w));
    uint2 o; o.x = *reinterpret_cast<uint32_t*>(&h0); o.y = *reinterpret_cast<uint32_t*>(&h1);
    reinterpret_cast<uint2*>(out)[i] = o;
}

// ---------------- split-K reduction: dbc (+fp16 copy) ----------------
__global__ void reduce_split_k(float* __restrict__ dbc)
{
    int i = blockIdx.x * 256 + threadIdx.x;
    if (i >= NROWS * DBC_COLS) return;
    float s = 0.0f;
#pragma unroll
    for (int z = 0; z < SPLITK; z++)
        s += g_sp[(size_t)z * NROWS * DBC_COLS + i];
    dbc[i] = s;
    g_dbch[i] = __float2half_rn(s);
}

// ---------------- weight transpose to fp16 ----------------
__global__ void transpose_h(const float* __restrict__ in, __half* __restrict__ out, int K, int N)
{
    __shared__ float t[32][33];
    const int n0 = blockIdx.x * 32, k0 = blockIdx.y * 32;
    for (int r = threadIdx.y; r < 32; r += 8)
        t[r][threadIdx.x] = in[(size_t)(k0 + r) * N + n0 + threadIdx.x];
    __syncthreads();
    for (int r = threadIdx.y; r < 32; r += 8)
        out[(size_t)(n0 + r) * K + k0 + threadIdx.x] = __float2half_rn(t[threadIdx.x][r]);
}

// ---------------- causal depthwise conv1d + silu (fp16 in/out, fp32 math) ----------------
__global__ void conv_silu_h(const float* __restrict__ conv_w,
                            const float* __restrict__ conv_b)
{
    int idx = blockIdx.x * 256 + threadIdx.x;
    if (idx >= NROWS * (D_INNER / 4)) return;
    int d4  = idx & (D_INNER / 4 - 1);
    int row = idx >> 9;
    int l   = row & (SEQ - 1);
    int b   = row >> 11;
    int d   = d4 * 4;

    const float4* cw4 = reinterpret_cast<const float4*>(conv_w);
    float4 wa = cw4[d + 0];
    float4 wb = cw4[d + 1];
    float4 wc = cw4[d + 2];
    float4 wd = cw4[d + 3];
    float4 acc = *reinterpret_cast<const float4*>(conv_b + d);

    const size_t base = ((size_t)b * SEQ) * (2 * D_INNER) + d;
    float4 xv[4];
#pragma unroll
    for (int k = 0; k < 4; k++) {
        int ll = l - 3 + k;
        if (ll >= 0) {
            uint2 hv = *reinterpret_cast<const uint2*>(&g_xrh[base + (size_t)ll * (2 * D_INNER)]);
            float2 f0 = __half22float2(*reinterpret_cast<__half2*>(&hv.x));
            float2 f1 = __half22float2(*reinterpret_cast<__half2*>(&hv.y));
            xv[k] = make_float4(f0.x, f0.y, f1.x, f1.y);
        } else {
            xv[k] = make_float4(0.f, 0.f, 0.f, 0.f);
        }
    }
    acc.x += xv[0].x * wa.x + xv[1].x * wa.y + xv[2].x * wa.z + xv[3].x * wa.w;
    acc.y += xv[0].y * wb.x + xv[1].y * wb.y + xv[2].y * wb.z + xv[3].y * wb.w;
    acc.z += xv[0].z * wc.x + xv[1].z * wc.y + xv[2].z * wc.z + xv[3].z * wc.w;
    acc.w += xv[0].w * wd.x + xv[1].w * wd.y + xv[2].w * wd.z + xv[3].w * wd.w;

    __half2 h0 = __float22half2_rn(make_float2(silu_f(acc.x), silu_f(acc.y)));
    __half2 h1 = __float22half2_rn(make_float2(silu_f(acc.z), silu_f(acc.w)));
    uint2 oh; oh.x = *reinterpret_cast<uint32_t*>(&h0); oh.y = *reinterpret_cast<uint32_t*>(&h1);
    *reinterpret_cast<uint2*>(&g_uh[(size_t)row * D_INNER + d]) = oh;
}

// ---------------- selective scan: 8 lanes x 2 states per thread, 32 d/CTA ----------------
// grid (64, 2) = 128 CTAs (one wave). dt fp32; u/res fp16 in; y fp16 out.
#define TCH 32
__global__ __launch_bounds__(256) void scan_k(
    const float* __restrict__ A_log,
    const float* __restrict__ Dv)
{
    __shared__ float s_dt [2][TCH][32];
    __shared__ float s_u  [2][TCH][32];
    __shared__ float s_res[2][TCH][32];
    __shared__ float s_bc [2][TCH][32];   // [0:16)=B, [16:32)=C
    __shared__ float s_y  [TCH][32];

    const int b    = blockIdx.y;
    const int d0   = blockIdx.x * 32;
    const int tid  = threadIdx.x;
    const int dloc = tid >> 3;    // 0..31
    const int n    = tid & 7;     // 0..7; thread owns states n and n+8
    const int d    = d0 + dloc;

    const float A0 = -__expf(A_log[d * D_STATE + n]);
    const float A1 = -__expf(A_log[d * D_STATE + n + 8]);
    const float Dd = Dv[d];
    float h0 = 0.0f, h1 = 0.0f;
    const size_t rowBase = (size_t)b * SEQ;

    auto load_chunk = [&](int l0, int buf) {
#pragma unroll
        for (int p = 0; p < 4; p++) {
            int e = p * 256 + tid, row = e >> 5, col = e & 31;
            size_t gRow = rowBase + l0 + row;
            s_dt [buf][row][col] = g_dt[gRow * D_INNER + d0 + col];
            s_u  [buf][row][col] = __half2float(g_uh[gRow * D_INNER + d0 + col]);
            s_res[buf][row][col] = __half2float(g_xrh[gRow * (2 * D_INNER) + D_INNER + d0 + col]);
            s_bc [buf][row][col] = g_dbc[gRow * DBC_COLS + DT_RANK + col];
        }
    };

    load_chunk(0, 0);
    __syncthreads();

    const int NCH = SEQ / TCH;
    for (int c = 0; c < NCH; c++) {
        const int buf = c & 1;
        if (c + 1 < NCH) load_chunk((c + 1) * TCH, buf ^ 1);

#pragma unroll 8
        for (int t = 0; t < TCH; t++) {
            float dt = s_dt[buf][t][dloc];
            float u  = s_u [buf][t][dloc];
            float B0 = s_bc[buf][t][n];
            float B1 = s_bc[buf][t][n + 8];
            float C0 = s_bc[buf][t][16 + n];
            float C1 = s_bc[buf][t][24 + n];
            float du = dt * u;
            h0 = fmaf(h0, __expf(dt * A0), du * B0);
            h1 = fmaf(h1, __expf(dt * A1), du * B1);
            float v = fmaf(h1, C1, h0 * C0);
            v += __shfl_xor_sync(0xffffffffu, v, 4);
            v += __shfl_xor_sync(0xffffffffu, v, 2);
            v += __shfl_xor_sync(0xffffffffu, v, 1);
            if (n == 0) s_y[t][dloc] = fmaf(Dd, u, v);
        }
        __syncthreads();

        // gated, coalesced y write (fp16)
#pragma unroll
        for (int p = 0; p < 4; p++) {
            int e = p * 256 + tid, row = e >> 5, col = e & 31;
            float r = s_res[buf][row][col];
            g_yh[(rowBase + c * TCH + row) * D_INNER + d0 + col] =
                __float2half_rn(s_y[row][col] * silu_f(r));
        }
        __syncthreads();
    }
}

// ---------------- launch ----------------
extern "C" void kernel_launch(void* const* d_in, const int* in_sizes, int n_in,
                              void* d_out, int out_size)
{
    const float* x          = (const float*)d_in[0];
    const float* in_proj_w  = (const float*)d_in[1];
    const float* conv_w     = (const float*)d_in[2];
    const float* conv_b     = (const float*)d_in[3];
    const float* x_proj_w   = (const float*)d_in[4];
    const float* dt_proj_w  = (const float*)d_in[5];
    const float* dt_proj_b  = (const float*)d_in[6];
    const float* A_log      = (const float*)d_in[7];
    const float* Dv         = (const float*)d_in[8];
    const float* out_proj_w = (const float*)d_in[9];
    float* out = (float*)d_out;

    float*  dbc  = nullptr; cudaGetSymbolAddress((void**)&dbc,  g_dbc);
    float*  dt   = nullptr; cudaGetSymbolAddress((void**)&dt,   g_dt);
    float*  sp   = nullptr; cudaGetSymbolAddress((void**)&sp,   g_sp);
    __half* xrh  = nullptr; cudaGetSymbolAddress((void**)&xrh,  g_xrh);
    __half* xh   = nullptr; cudaGetSymbolAddress((void**)&xh,   g_xh);
    __half* uh   = nullptr; cudaGetSymbolAddress((void**)&uh,   g_uh);
    __half* dbch = nullptr; cudaGetSymbolAddress((void**)&dbch, g_dbch);
    __half* yh   = nullptr; cudaGetSymbolAddress((void**)&yh,   g_yh);
    __half* wt   = nullptr; cudaGetSymbolAddress((void**)&wt,   g_wt);

    static int smem_set = 0;
    if (!smem_set) {
        cudaFuncSetAttribute(gemm_h, cudaFuncAttributeMaxDynamicSharedMemorySize, GEMM_SMEM);
        smem_set = 1;
    }

    dim3 tb(32, 8);

    // idx 0: x -> fp16
    cvt_h<<<(NROWS * D_MODEL / 4 + 255) / 256, 256>>>(x, xh, NROWS * D_MODEL / 4);
    // idx 1-2: transposes needed by in_proj GEMM
    transpose_h<<<dim3(128, 32), tb>>>(in_proj_w, wt + WT_IN, 1024, 4096);
    transpose_h<<<dim3(3, 64), tb>>>(x_proj_w, wt + WT_XP, 2048, 96);

    // idx 3 (ncu-captured): in_proj GEMM (4096 x 4096, K=1024), fp16 output -> xrh
    gemm_h<<<dim3(32, 32), 256, GEMM_SMEM>>>(
        xh, D_MODEL, wt + WT_IN, D_MODEL, nullptr, (float*)xrh, 2 * D_INNER, D_MODEL, 2, 0);

    // idx 4-5: remaining transposes
    transpose_h<<<dim3(64, 2), tb>>>(dt_proj_w, wt + WT_DT, 64, 2048);
    transpose_h<<<dim3(32, 64), tb>>>(out_proj_w, wt + WT_OUT, 2048, 1024);

    // idx 6: conv + silu (fp16 in/out) -> uh
    conv_silu_h<<<(NROWS * (D_INNER / 4) + 255) / 256, 256>>>(conv_w, conv_b);

    // idx 7-8: dbc = u @ x_proj_w (4096x96, K=2048) split-K x8 + reduce
    gemm_h<<<dim3(1, 32, SPLITK), 256, GEMM_SMEM>>>(
        uh, D_INNER, wt + WT_XP, D_INNER, nullptr, sp, DBC_COLS, D_INNER / SPLITK, 0,
        (size_t)NROWS * DBC_COLS);
    reduce_split_k<<<(NROWS * DBC_COLS + 255) / 256, 256>>>(dbc);

    // idx 9: dt = softplus(dbc[:, :64] @ dt_proj_w + b)  (4096x2048, K=64), fp32
    gemm_h<<<dim3(16, 32), 256, GEMM_SMEM>>>(
        dbch, DBC_COLS, wt + WT_DT, DT_RANK, dt_proj_b, dt, D_INNER, DT_RANK, 1, 0);

    // idx 10: selective scan + gating -> yh (fp16)
    scan_k<<<dim3(D_INNER / 32, BATCH), 256>>>(A_log, Dv);

    // idx 11: out = y @ out_proj_w  (4096x1024, K=2048), fp32 output
    gemm_h<<<dim3(8, 32), 256, GEMM_SMEM>>>(
        yh, D_INNER, wt + WT_OUT, D_INNER, nullptr, out, D_MODEL, D_INNER, 0, 0);
}

// round 17
// speedup vs baseline: 1.8201x; 1.0068x over previous
#include <cuda_runtime.h>
#include <cuda_fp16.h>
#include <cstdint>
#include <cstddef>

// ---------------- problem constants ----------------
#define D_MODEL  1024
#define D_STATE  16
#define D_INNER  2048
#define DT_RANK  64
#define BATCH    2
#define SEQ      2048
#define NROWS    (BATCH * SEQ)           // 4096
#define DBC_COLS 96
#define SPLITK   8

// ---------------- scratch (static device globals; no allocation) ----------------
__device__ float  g_dbc [(size_t)NROWS * DBC_COLS];
__device__ float  g_dt  [(size_t)NROWS * D_INNER];
__device__ float  g_sp  [(size_t)SPLITK * NROWS * DBC_COLS];
__device__ __half g_xrh [(size_t)NROWS * (2 * D_INNER)];  // cols [0,2048)=xb, [2048,4096)=res
__device__ __half g_xh  [(size_t)NROWS * D_MODEL];
__device__ __half g_uh  [(size_t)NROWS * D_INNER];
__device__ __half g_dbch[(size_t)NROWS * DBC_COLS];
__device__ __half g_yh  [(size_t)NROWS * D_INNER];
__device__ __half g_wt  [(size_t)8 * 1024 * 1024];

// region offsets (halves)
#define WT_IN   ((size_t)0)
#define WT_XP   ((size_t)4096 * 1024)
#define WT_DT   (WT_XP + (size_t)96 * 2048)
#define WT_OUT  (WT_DT + (size_t)2048 * 64)

// ---------------- helpers ----------------
__device__ __forceinline__ float silu_f(float x) { return x / (1.0f + __expf(-x)); }
__device__ __forceinline__ float softplus_f(float x) { return (x > 20.0f) ? x : log1pf(__expf(x)); }
__device__ __forceinline__ uint32_t smem_u32(const void* p) {
    uint32_t a;
    asm("{ .reg .u64 t; cvta.to.shared.u64 t, %1; cvt.u32.u64 %0, t; }" : "=r"(a) : "l"(p));
    return a;
}
__device__ __forceinline__ void mma_f16(float* d, const uint32_t* a, const uint32_t* b) {
    asm volatile(
        "mma.sync.aligned.m16n8k16.row.col.f32.f16.f16.f32 "
        "{%0,%1,%2,%3}, {%4,%5,%6,%7}, {%8,%9}, {%0,%1,%2,%3};"
        : "+f"(d[0]), "+f"(d[1]), "+f"(d[2]), "+f"(d[3])
        : "r"(a[0]), "r"(a[1]), "r"(a[2]), "r"(a[3]), "r"(b[0]), "r"(b[1]));
}
__device__ __forceinline__ void ldsm4(uint32_t& r0, uint32_t& r1, uint32_t& r2, uint32_t& r3,
                                      uint32_t addr) {
    asm volatile("ldmatrix.sync.aligned.m8n8.x4.shared.b16 {%0,%1,%2,%3}, [%4];"
                 : "=r"(r0), "=r"(r1), "=r"(r2), "=r"(r3) : "r"(addr));
}
__device__ __forceinline__ void cpa16(uint32_t dst, const void* src) {
    asm volatile("cp.async.cg.shared.global [%0], [%1], 16;" :: "r"(dst), "l"(src));
}
__device__ __forceinline__ void cp_commit() {
    asm volatile("cp.async.commit_group;" ::: "memory");
}
template<int N> __device__ __forceinline__ void cp_wait() {
    asm volatile("cp.async.wait_group %0;" :: "n"(N) : "memory");
}
__device__ __forceinline__ void sts_zero16(uint32_t addr) {
    asm volatile("st.shared.v4.b32 [%0], {%1,%1,%1,%1};" :: "r"(addr), "r"(0u) : "memory");
}

// ---------------- fp16 tensor-core GEMM: block 128x128, 8 warps (32x64 tiles), ----------------
// 4-stage cp.async ring, 2 CTAs/SM -> 16 warps/SM.
// mode 0: fp32 store; mode 1: fp32 softplus(acc+bias); mode 2: fp16 store.
#define BKH 32
#define RSH 40                       // smem row stride in halves (80 B)
#define STG 4
#define GEMM_SMEM (STG * 256 * RSH * 2)   // 81920 B

__global__ __launch_bounds__(256, 2) void gemm_h(
    const __half* __restrict__ A, int lda,
    const __half* __restrict__ Wt, int ldw,
    const float* __restrict__ bias,
    float* __restrict__ C, int N_total, int K_sub, int mode, size_t Cstride)
{
    extern __shared__ __half sh[];
    const uint32_t sA = smem_u32(sh);
    const uint32_t sB = sA + STG * 128 * RSH * 2;

    const int tid  = threadIdx.x;
    const int w    = tid >> 5;
    const int l    = tid & 31;
    const int mBase = blockIdx.y * 128;
    const int nBase = blockIdx.x * 128;
    const int kOff  = blockIdx.z * K_sub;

    const int wm = (w & 3) * 32;      // 4 warps in M
    const int wn = (w >> 2) * 64;     // 2 warps in N

    const int aRowOff = (l & 7) + ((l >> 3) & 1) * 8;
    const int aColH   = ((l >> 4) & 1) * 8;
    const int bRowOff = (l & 7) + ((l >> 4) & 1) * 8;
    const int bColH   = ((l >> 3) & 1) * 8;

    float acc[2][8][4];
#pragma unroll
    for (int i = 0; i < 2; i++)
#pragma unroll
        for (int j = 0; j < 8; j++)
#pragma unroll
            for (int q = 0; q < 4; q++) acc[i][j][q] = 0.0f;

    // loader: 256 threads, A/B 128 rows x 32 halves; thread -> row tid>>1, 16-half chunk tid&1
    const int ldRow = tid >> 1;
    const int ldC   = (tid & 1) * 16;

    auto issue = [&](int stage, int k0) {
        const __half* ap = A + (size_t)(mBase + ldRow) * lda + kOff + k0 + ldC;
        uint32_t ad = sA + (uint32_t)(stage * 128 + ldRow) * (RSH * 2) + (uint32_t)ldC * 2;
        cpa16(ad, ap);
        cpa16(ad + 16, ap + 8);
        int n = nBase + ldRow;
        uint32_t bd = sB + (uint32_t)(stage * 128 + ldRow) * (RSH * 2) + (uint32_t)ldC * 2;
        if (n < N_total) {
            const __half* bp = Wt + (size_t)n * ldw + kOff + k0 + ldC;
            cpa16(bd, bp);
            cpa16(bd + 16, bp + 8);
        } else {
            sts_zero16(bd);
            sts_zero16(bd + 16);
        }
    };

    auto compute = [&](int stage) {
        const uint32_t aB = sA + (uint32_t)((stage * 128 + wm + aRowOff) * RSH + aColH) * 2;
        const uint32_t bB = sB + (uint32_t)((stage * 128 + wn + bRowOff) * RSH + bColH) * 2;
#pragma unroll
        for (int s = 0; s < 2; s++) {
            uint32_t af[2][4], bf[8][2];
#pragma unroll
            for (int i = 0; i < 2; i++)
                ldsm4(af[i][0], af[i][1], af[i][2], af[i][3],
                      aB + (uint32_t)((i * 16 * RSH + s * 16) * 2));
#pragma unroll
            for (int jj = 0; jj < 4; jj++)
                ldsm4(bf[2 * jj][0], bf[2 * jj][1], bf[2 * jj + 1][0], bf[2 * jj + 1][1],
                      bB + (uint32_t)((jj * 16 * RSH + s * 16) * 2));
#pragma unroll
            for (int i = 0; i < 2; i++)
#pragma unroll
                for (int j = 0; j < 8; j++)
                    mma_f16(acc[i][j], af[i], bf[j]);
        }
    };

    const int nt = K_sub / BKH;
    int fetch = 0;
    // padded prologue: ALWAYS commit STG-1 groups (empty beyond nt) so the
    // uniform cp_wait<STG-2> arithmetic retires exactly chunk t at iteration t.
    for (int p = 0; p < STG - 1; p++) {
        if (fetch < nt) { issue(fetch % STG, fetch * BKH); fetch++; }
        cp_commit();
    }

    for (int t = 0; t < nt; t++) {
        cp_wait<STG - 2>();
        __syncthreads();
        if (fetch < nt) { issue(fetch % STG, fetch * BKH); fetch++; }
        cp_commit();                    // always commit to keep counts uniform
        compute(t % STG);
    }

    // epilogue
    float*  Cf = C + (size_t)blockIdx.z * Cstride;
    __half* Ch = reinterpret_cast<__half*>(C);
#pragma unroll
    for (int i = 0; i < 2; i++) {
        int r0 = mBase + wm + i * 16 + (l >> 2);
#pragma unroll
        for (int j = 0; j < 8; j++) {
            int cc = nBase + wn + j * 8 + (l & 3) * 2;
            if (cc < N_total) {
                float2 v0, v1;
                v0.x = acc[i][j][0]; v0.y = acc[i][j][1];
                v1.x = acc[i][j][2]; v1.y = acc[i][j][3];
                if (mode == 2) {
                    __half2 h0 = __float22half2_rn(v0);
                    __half2 h1 = __float22half2_rn(v1);
                    *reinterpret_cast<__half2*>(Ch + (size_t)r0 * N_total + cc)       = h0;
                    *reinterpret_cast<__half2*>(Ch + (size_t)(r0 + 8) * N_total + cc) = h1;
                } else {
                    if (mode == 1) {
                        float b0 = bias[cc], b1 = bias[cc + 1];
                        v0.x = softplus_f(v0.x + b0); v0.y = softplus_f(v0.y + b1);
                        v1.x = softplus_f(v1.x + b0); v1.y = softplus_f(v1.y + b1);
                    }
                    *reinterpret_cast<float2*>(Cf + (size_t)r0 * N_total + cc)       = v0;
                    *reinterpret_cast<float2*>(Cf + (size_t)(r0 + 8) * N_total + cc) = v1;
                }
            }
        }
    }
}

// ---------------- fused prep: x->fp16 + all 4 weight transposes ----------------
// block ranges: [0,4096) cvt x; [4096,8192) in_proj; [8192,8384) x_proj;
//               [8384,8512) dt_proj; [8512,10560) out_proj
#define PREP_CTAS 10560

__device__ __forceinline__ void tr32(const float* __restrict__ in, __half* __restrict__ out,
                                     int K, int N, int bx, int by, int tx, int ty,
                                     float (*t)[33])
{
    const int n0 = bx * 32, k0 = by * 32;
    for (int r = ty; r < 32; r += 8)
        t[r][tx] = in[(size_t)(k0 + r) * N + n0 + tx];
    __syncthreads();
    for (int r = ty; r < 32; r += 8)
        out[(size_t)(n0 + r) * K + k0 + tx] = __float2half_rn(t[tx][r]);
}

__global__ __launch_bounds__(256) void prep_k(
    const float* __restrict__ x,
    const float* __restrict__ w_in,
    const float* __restrict__ w_xp,
    const float* __restrict__ w_dt,
    const float* __restrict__ w_out,
    __half* __restrict__ xh,
    __half* __restrict__ wt)
{
    __shared__ float t[32][33];
    const int bid = blockIdx.x;
    const int tid = threadIdx.x;
    const int tx  = tid & 31;
    const int ty  = tid >> 5;

    if (bid < 4096) {
        int i = bid * 256 + tid;                 // 1,048,576 float4s total
        float4 v = reinterpret_cast<const float4*>(x)[i];
        __half2 h0 = __float22half2_rn(make_float2(v.x, v.y));
        __half2 h1 = __float22half2_rn(make_float2(v.z, v.w));
        uint2 o; o.x = *reinterpret_cast<uint32_t*>(&h0); o.y = *reinterpret_cast<uint32_t*>(&h1);
        reinterpret_cast<uint2*>(xh)[i] = o;
    } else if (bid < 8192) {
        int q = bid - 4096;                      // in_proj: K=1024, N=4096, grid 128x32
        tr32(w_in, wt + WT_IN, 1024, 4096, q % 128, q / 128, tx, ty, t);
    } else if (bid < 8384) {
        int q = bid - 8192;                      // x_proj: K=2048, N=96, grid 3x64
        tr32(w_xp, wt + WT_XP, 2048, 96, q % 3, q / 3, tx, ty, t);
    } else if (bid < 8512) {
        int q = bid - 8384;                      // dt_proj: K=64, N=2048, grid 64x2
        tr32(w_dt, wt + WT_DT, 64, 2048, q % 64, q / 64, tx, ty, t);
    } else {
        int q = bid - 8512;                      // out_proj: K=2048, N=1024, grid 32x64
        tr32(w_out, wt + WT_OUT, 2048, 1024, q % 32, q / 32, tx, ty, t);
    }
}

// ---------------- split-K reduction: dbc (+fp16 copy) ----------------
__global__ void reduce_split_k(float* __restrict__ dbc)
{
    int i = blockIdx.x * 256 + threadIdx.x;
    if (i >= NROWS * DBC_COLS) return;
    float s = 0.0f;
#pragma unroll
    for (int z = 0; z < SPLITK; z++)
        s += g_sp[(size_t)z * NROWS * DBC_COLS + i];
    dbc[i] = s;
    g_dbch[i] = __float2half_rn(s);
}

// ---------------- causal depthwise conv1d + silu (fp16 in/out, fp32 math) ----------------
__global__ void conv_silu_h(const float* __restrict__ conv_w,
                            const float* __restrict__ conv_b)
{
    int idx = blockIdx.x * 256 + threadIdx.x;
    if (idx >= NROWS * (D_INNER / 4)) return;
    int d4  = idx & (D_INNER / 4 - 1);
    int row = idx >> 9;
    int l   = row & (SEQ - 1);
    int b   = row >> 11;
    int d   = d4 * 4;

    const float4* cw4 = reinterpret_cast<const float4*>(conv_w);
    float4 wa = cw4[d + 0];
    float4 wb = cw4[d + 1];
    float4 wc = cw4[d + 2];
    float4 wd = cw4[d + 3];
    float4 acc = *reinterpret_cast<const float4*>(conv_b + d);

    const size_t base = ((size_t)b * SEQ) * (2 * D_INNER) + d;
    float4 xv[4];
#pragma unroll
    for (int k = 0; k < 4; k++) {
        int ll = l - 3 + k;
        if (ll >= 0) {
            uint2 hv = *reinterpret_cast<const uint2*>(&g_xrh[base + (size_t)ll * (2 * D_INNER)]);
            float2 f0 = __half22float2(*reinterpret_cast<__half2*>(&hv.x));
            float2 f1 = __half22float2(*reinterpret_cast<__half2*>(&hv.y));
            xv[k] = make_float4(f0.x, f0.y, f1.x, f1.y);
        } else {
            xv[k] = make_float4(0.f, 0.f, 0.f, 0.f);
        }
    }
    acc.x += xv[0].x * wa.x + xv[1].x * wa.y + xv[2].x * wa.z + xv[3].x * wa.w;
    acc.y += xv[0].y * wb.x + xv[1].y * wb.y + xv[2].y * wb.z + xv[3].y * wb.w;
    acc.z += xv[0].z * wc.x + xv[1].z * wc.y + xv[2].z * wc.z + xv[3].z * wc.w;
    acc.w += xv[0].w * wd.x + xv[1].w * wd.y + xv[2].w * wd.z + xv[3].w * wd.w;

    __half2 h0 = __float22half2_rn(make_float2(silu_f(acc.x), silu_f(acc.y)));
    __half2 h1 = __float22half2_rn(make_float2(silu_f(acc.z), silu_f(acc.w)));
    uint2 oh; oh.x = *reinterpret_cast<uint32_t*>(&h0); oh.y = *reinterpret_cast<uint32_t*>(&h1);
    *reinterpret_cast<uint2*>(&g_uh[(size_t)row * D_INNER + d]) = oh;
}

// ---------------- selective scan: 8 lanes x 2 states per thread, 32 d/CTA ----------------
// grid (64, 2) = 128 CTAs. dt fp32; u/res fp16 in; y fp16 out.
#define TCH 32
__global__ __launch_bounds__(256) void scan_k(
    const float* __restrict__ A_log,
    const float* __restrict__ Dv)
{
    __shared__ float s_dt [2][TCH][32];
    __shared__ float s_u  [2][TCH][32];
    __shared__ float s_res[2][TCH][32];
    __shared__ float s_bc [2][TCH][32];   // [0:16)=B, [16:32)=C
    __shared__ float s_y  [TCH][32];

    const int b    = blockIdx.y;
    const int d0   = blockIdx.x * 32;
    const int tid  = threadIdx.x;
    const int dloc = tid >> 3;    // 0..31
    const int n    = tid & 7;     // 0..7; thread owns states n and n+8
    const int d    = d0 + dloc;

    const float A0 = -__expf(A_log[d * D_STATE + n]);
    const float A1 = -__expf(A_log[d * D_STATE + n + 8]);
    const float Dd = Dv[d];
    float h0 = 0.0f, h1 = 0.0f;
    const size_t rowBase = (size_t)b * SEQ;

    auto load_chunk = [&](int l0, int buf) {
#pragma unroll
        for (int p = 0; p < 4; p++) {
            int e = p * 256 + tid, row = e >> 5, col = e & 31;
            size_t gRow = rowBase + l0 + row;
            s_dt [buf][row][col] = g_dt[gRow * D_INNER + d0 + col];
            s_u  [buf][row][col] = __half2float(g_uh[gRow * D_INNER + d0 + col]);
            s_res[buf][row][col] = __half2float(g_xrh[gRow * (2 * D_INNER) + D_INNER + d0 + col]);
            s_bc [buf][row][col] = g_dbc[gRow * DBC_COLS + DT_RANK + col];
        }
    };

    load_chunk(0, 0);
    __syncthreads();

    const int NCH = SEQ / TCH;
    for (int c = 0; c < NCH; c++) {
        const int buf = c & 1;
        if (c + 1 < NCH) load_chunk((c + 1) * TCH, buf ^ 1);

#pragma unroll 8
        for (int t = 0; t < TCH; t++) {
            float dt = s_dt[buf][t][dloc];
            float u  = s_u [buf][t][dloc];
            float B0 = s_bc[buf][t][n];
            float B1 = s_bc[buf][t][n + 8];
            float C0 = s_bc[buf][t][16 + n];
            float C1 = s_bc[buf][t][24 + n];
            float du = dt * u;
            h0 = fmaf(h0, __expf(dt * A0), du * B0);
            h1 = fmaf(h1, __expf(dt * A1), du * B1);
            float v = fmaf(h1, C1, h0 * C0);
            v += __shfl_xor_sync(0xffffffffu, v, 4);
            v += __shfl_xor_sync(0xffffffffu, v, 2);
            v += __shfl_xor_sync(0xffffffffu, v, 1);
            if (n == 0) s_y[t][dloc] = fmaf(Dd, u, v);
        }
        __syncthreads();

        // gated, coalesced y write (fp16)
#pragma unroll
        for (int p = 0; p < 4; p++) {
            int e = p * 256 + tid, row = e >> 5, col = e & 31;
            float r = s_res[buf][row][col];
            g_yh[(rowBase + c * TCH + row) * D_INNER + d0 + col] =
                __float2half_rn(s_y[row][col] * silu_f(r));
        }
        __syncthreads();
    }
}

// ---------------- launch ----------------
extern "C" void kernel_launch(void* const* d_in, const int* in_sizes, int n_in,
                              void* d_out, int out_size)
{
    const float* x          = (const float*)d_in[0];
    const float* in_proj_w  = (const float*)d_in[1];
    const float* conv_w     = (const float*)d_in[2];
    const float* conv_b     = (const float*)d_in[3];
    const float* x_proj_w   = (const float*)d_in[4];
    const float* dt_proj_w  = (const float*)d_in[5];
    const float* dt_proj_b  = (const float*)d_in[6];
    const float* A_log      = (const float*)d_in[7];
    const float* Dv         = (const float*)d_in[8];
    const float* out_proj_w = (const float*)d_in[9];
    float* out = (float*)d_out;

    float*  dbc  = nullptr; cudaGetSymbolAddress((void**)&dbc,  g_dbc);
    float*  dt   = nullptr; cudaGetSymbolAddress((void**)&dt,   g_dt);
    float*  sp   = nullptr; cudaGetSymbolAddress((void**)&sp,   g_sp);
    __half* xrh  = nullptr; cudaGetSymbolAddress((void**)&xrh,  g_xrh);
    __half* xh   = nullptr; cudaGetSymbolAddress((void**)&xh,   g_xh);
    __half* uh   = nullptr; cudaGetSymbolAddress((void**)&uh,   g_uh);
    __half* dbch = nullptr; cudaGetSymbolAddress((void**)&dbch, g_dbch);
    __half* yh   = nullptr; cudaGetSymbolAddress((void**)&yh,   g_yh);
    __half* wt   = nullptr; cudaGetSymbolAddress((void**)&wt,   g_wt);

    static int smem_set = 0;
    if (!smem_set) {
        cudaFuncSetAttribute(gemm_h, cudaFuncAttributeMaxDynamicSharedMemorySize, GEMM_SMEM);
        smem_set = 1;
    }

    // idx 0: fused prep (x->fp16 + all weight transposes)
    prep_k<<<PREP_CTAS, 256>>>(x, in_proj_w, x_proj_w, dt_proj_w, out_proj_w, xh, wt);

    // idx 1: in_proj GEMM (4096 x 4096, K=1024), fp16 output -> xrh
    gemm_h<<<dim3(32, 32), 256, GEMM_SMEM>>>(
        xh, D_MODEL, wt + WT_IN, D_MODEL, nullptr, (float*)xrh, 2 * D_INNER, D_MODEL, 2, 0);

    // idx 2: conv + silu (fp16 in/out) -> uh
    conv_silu_h<<<(NROWS * (D_INNER / 4) + 255) / 256, 256>>>(conv_w, conv_b);

    // idx 3 (ncu-captured): dbc = u @ x_proj_w (4096x96, K=2048) split-K x8
    gemm_h<<<dim3(1, 32, SPLITK), 256, GEMM_SMEM>>>(
        uh, D_INNER, wt + WT_XP, D_INNER, nullptr, sp, DBC_COLS, D_INNER / SPLITK, 0,
        (size_t)NROWS * DBC_COLS);

    // idx 4: reduce split-K partials
    reduce_split_k<<<(NROWS * DBC_COLS + 255) / 256, 256>>>(dbc);

    // idx 5: dt = softplus(dbc[:, :64] @ dt_proj_w + b)  (4096x2048, K=64), fp32
    gemm_h<<<dim3(16, 32), 256, GEMM_SMEM>>>(
        dbch, DBC_COLS, wt + WT_DT, DT_RANK, dt_proj_b, dt, D_INNER, DT_RANK, 1, 0);

    // idx 6: selective scan + gating -> yh (fp16)
    scan_k<<<dim3(D_INNER / 32, BATCH), 256>>>(A_log, Dv);

    // idx 7: out = y @ out_proj_w  (4096x1024, K=2048), fp32 output
    gemm_h<<<dim3(8, 32), 256, GEMM_SMEM>>>(
        yh, D_INNER, wt + WT_OUT, D_INNER, nullptr, out, D_MODEL, D_INNER, 0, 0);
}